// round 4
// baseline (speedup 1.0000x reference)
#include <cuda_runtime.h>
#include <stdint.h>

// MultiIndexSelect: out[to_s[j]] = mat_s[from_s[j]] for s in {0,1,2}, j in [0,L)
// D = 64 floats = 16 float4 = 256 B per row.
//
// Persistent-block version: grid sized to one resident wave; each block
// grid-strides over 64-row tiles. Indices for the NEXT tile are prefetched
// while the current tile's payload loads / stores are in flight, so the
// index->payload serial dependency never stalls the load pipeline.
// 16 lanes per row (one float4 each), 4 rows per thread per tile (MLP=4),
// streaming stores (output written once, never re-read).

#define D4 16
#define RPT 4
#define ROWS_PER_TILE 64

__device__ __forceinline__ void store_streaming(float4* p, float4 v) {
    asm volatile("st.global.cs.v4.f32 [%0], {%1, %2, %3, %4};"
                 :: "l"(p), "f"(v.x), "f"(v.y), "f"(v.z), "f"(v.w) : "memory");
}

__global__ void __launch_bounds__(256)
multi_index_select_kernel(
    const float4* __restrict__ m0,
    const float4* __restrict__ m1,
    const float4* __restrict__ m2,
    const int*    __restrict__ f0,
    const int*    __restrict__ f1,
    const int*    __restrict__ f2,
    const int*    __restrict__ t0,
    const int*    __restrict__ t1,
    const int*    __restrict__ t2,
    float4*       __restrict__ out,
    int tiles_per_seg,     // L / ROWS_PER_TILE
    int num_tiles)         // 3 * tiles_per_seg
{
    const int lane = threadIdx.x & (D4 - 1);
    const int rsub = threadIdx.x >> 4;

    int t = blockIdx.x;
    if (t >= num_tiles) return;

    // Prologue: indices for the first tile (block-uniform segment)
    int seg = t / tiles_per_seg;
    const float4* __restrict__ src = (seg == 0) ? m0 : (seg == 1) ? m1 : m2;
    const int*    __restrict__ fi  = (seg == 0) ? f0 : (seg == 1) ? f1 : f2;
    const int*    __restrict__ ti  = (seg == 0) ? t0 : (seg == 1) ? t1 : t2;
    int base = (t - seg * tiles_per_seg) * ROWS_PER_TILE + rsub;

    int fr[RPT], to[RPT];
    #pragma unroll
    for (int i = 0; i < RPT; i++) {
        fr[i] = __ldg(&fi[base + 16 * i]);
        to[i] = __ldg(&ti[base + 16 * i]);
    }

    while (true) {
        // Payload loads for current tile (4 independent LDG.128)
        float4 v[RPT];
        #pragma unroll
        for (int i = 0; i < RPT; i++) {
            v[i] = __ldg(&src[(size_t)fr[i] * D4 + lane]);
        }

        // Prefetch next tile's indices while payload loads are in flight
        int tn = t + gridDim.x;
        int frn[RPT], ton[RPT];
        const float4* __restrict__ srcn = src;
        if (tn < num_tiles) {
            int segn = tn / tiles_per_seg;
            const int* __restrict__ fin = (segn == 0) ? f0 : (segn == 1) ? f1 : f2;
            const int* __restrict__ tin = (segn == 0) ? t0 : (segn == 1) ? t1 : t2;
            srcn = (segn == 0) ? m0 : (segn == 1) ? m1 : m2;
            int basen = (tn - segn * tiles_per_seg) * ROWS_PER_TILE + rsub;
            #pragma unroll
            for (int i = 0; i < RPT; i++) {
                frn[i] = __ldg(&fin[basen + 16 * i]);
                ton[i] = __ldg(&tin[basen + 16 * i]);
            }
        }

        // Streaming stores for current tile
        #pragma unroll
        for (int i = 0; i < RPT; i++) {
            store_streaming(&out[(size_t)to[i] * D4 + lane], v[i]);
        }

        if (tn >= num_tiles) break;
        t = tn;
        src = srcn;
        #pragma unroll
        for (int i = 0; i < RPT; i++) { fr[i] = frn[i]; to[i] = ton[i]; }
    }
}

extern "C" void kernel_launch(void* const* d_in, const int* in_sizes, int n_in,
                              void* d_out, int out_size)
{
    const float4* m0 = (const float4*)d_in[0];
    const float4* m1 = (const float4*)d_in[1];
    const float4* m2 = (const float4*)d_in[2];
    const int* f0 = (const int*)d_in[3];
    const int* f1 = (const int*)d_in[4];
    const int* f2 = (const int*)d_in[5];
    const int* t0 = (const int*)d_in[6];
    const int* t1 = (const int*)d_in[7];
    const int* t2 = (const int*)d_in[8];
    float4* out = (float4*)d_out;

    int L = in_sizes[3];                       // 400000
    int tiles_per_seg = L / ROWS_PER_TILE;     // 6250
    int num_tiles = 3 * tiles_per_seg;         // 18750

    // One resident wave: occupancy-sized persistent grid (host-side queries,
    // no allocation, graph-capture safe).
    int blocks_per_sm = 0;
    cudaOccupancyMaxActiveBlocksPerMultiprocessor(
        &blocks_per_sm, multi_index_select_kernel, 256, 0);
    if (blocks_per_sm < 1) blocks_per_sm = 1;
    int num_sms = 148;
    cudaDeviceGetAttribute(&num_sms, cudaDevAttrMultiProcessorCount, 0);

    int grid = blocks_per_sm * num_sms;
    if (grid > num_tiles) grid = num_tiles;

    multi_index_select_kernel<<<grid, 256>>>(
        m0, m1, m2, f0, f1, f2, t0, t1, t2, out, tiles_per_seg, num_tiles);
}

// round 8
// speedup vs baseline: 1.0928x; 1.0928x over previous
#include <cuda_runtime.h>
#include <stdint.h>

// MultiIndexSelect: out[to_s[j]] = mat_s[from_s[j]] for s in {0,1,2}, j in [0,L)
// D = 64 floats = 256 B per row.
//
// R8: 8 lanes per row, each moving 32 B via Blackwell 256-bit loads
// (ld.global.nc.L2::evict_last.v8.b32 — ptxas requires v8.b32 with the
// evict_last hint on sm_103). Source reads are evict-last (1.45x reuse,
// ~L2-sized per segment); output stores are evict-first .cs (written once).
// RPT=2 rows/thread -> 64 rows per 256-thread block; 6250 blocks/segment.

#define RPT 2
#define LANES 8               // threads per row
#define ROWS_PER_BLOCK 64     // 256 threads / 8 lanes * RPT
#define BLOCKS_PER_SEG 6250   // L / ROWS_PER_BLOCK

__device__ __forceinline__ void load_evict_last_32B(const float* p, uint32_t* r) {
    asm volatile(
        "ld.global.nc.L2::evict_last.v8.b32 {%0, %1, %2, %3, %4, %5, %6, %7}, [%8];"
        : "=r"(r[0]), "=r"(r[1]), "=r"(r[2]), "=r"(r[3]),
          "=r"(r[4]), "=r"(r[5]), "=r"(r[6]), "=r"(r[7])
        : "l"(p) : "memory");
}

__device__ __forceinline__ void store_streaming_32B(float* p, const uint32_t* r) {
    asm volatile("st.global.cs.v4.b32 [%0], {%1, %2, %3, %4};"
                 :: "l"(p), "r"(r[0]), "r"(r[1]), "r"(r[2]), "r"(r[3]) : "memory");
    asm volatile("st.global.cs.v4.b32 [%0], {%1, %2, %3, %4};"
                 :: "l"(p + 4), "r"(r[4]), "r"(r[5]), "r"(r[6]), "r"(r[7]) : "memory");
}

__global__ void __launch_bounds__(256)
multi_index_select_kernel(
    const float* __restrict__ m0,
    const float* __restrict__ m1,
    const float* __restrict__ m2,
    const int*   __restrict__ f0,
    const int*   __restrict__ f1,
    const int*   __restrict__ f2,
    const int*   __restrict__ t0,
    const int*   __restrict__ t1,
    const int*   __restrict__ t2,
    float*       __restrict__ out)
{
    // Block-uniform segment selection (uniform-register pointers, no divergence)
    const int seg = blockIdx.x / BLOCKS_PER_SEG;          // 0, 1, 2
    const int segblk = blockIdx.x - seg * BLOCKS_PER_SEG;

    const float* __restrict__ src = (seg == 0) ? m0 : (seg == 1) ? m1 : m2;
    const int*   __restrict__ fi  = (seg == 0) ? f0 : (seg == 1) ? f1 : f2;
    const int*   __restrict__ ti  = (seg == 0) ? t0 : (seg == 1) ? t1 : t2;

    const int lane = threadIdx.x & (LANES - 1);           // 0..7, 32B slot in row
    const int rsub = threadIdx.x >> 3;                    // 0..31
    const int rbase = segblk * ROWS_PER_BLOCK + rsub;     // rows: rbase + 32*i

    // Phase 1: batch index loads
    int fr[RPT], to[RPT];
    #pragma unroll
    for (int i = 0; i < RPT; i++) {
        int r = rbase + 32 * i;
        fr[i] = __ldg(&fi[r]);
        to[i] = __ldg(&ti[r]);
    }

    // Phase 2: front-batch independent 32B payload loads (evict-last)
    uint32_t v[RPT][8];
    #pragma unroll
    for (int i = 0; i < RPT; i++) {
        load_evict_last_32B(&src[(size_t)fr[i] * 64 + lane * 8], v[i]);
    }

    // Phase 3: streaming stores (output written once, never re-read)
    #pragma unroll
    for (int i = 0; i < RPT; i++) {
        store_streaming_32B(&out[(size_t)to[i] * 64 + lane * 8], v[i]);
    }
}

extern "C" void kernel_launch(void* const* d_in, const int* in_sizes, int n_in,
                              void* d_out, int out_size)
{
    const float* m0 = (const float*)d_in[0];
    const float* m1 = (const float*)d_in[1];
    const float* m2 = (const float*)d_in[2];
    const int* f0 = (const int*)d_in[3];
    const int* f1 = (const int*)d_in[4];
    const int* f2 = (const int*)d_in[5];
    const int* t0 = (const int*)d_in[6];
    const int* t1 = (const int*)d_in[7];
    const int* t2 = (const int*)d_in[8];
    float* out = (float*)d_out;

    // 3 * 400000 rows / 64 rows per block = 18750 blocks exactly
    multi_index_select_kernel<<<3 * BLOCKS_PER_SEG, 256>>>(
        m0, m1, m2, f0, f1, f2, t0, t1, t2, out);
}